// round 5
// baseline (speedup 1.0000x reference)
#include <cuda_runtime.h>
#include <math.h>

#define BATCH     2000000
#define LAM       0.1
#define NBLOCKS   1184      // 148 SMs * 8
#define NTHREADS  256
#define NWARPS    ((NBLOCKS * NTHREADS) >> 5)
#define NCHUNKS   (BATCH / 32)

__device__ double g_part[NBLOCKS][3];
__device__ unsigned int g_ticket;   // zero-init; last block resets -> graph-replay safe

__device__ __forceinline__ double warp_reduce_d(double v) {
    #pragma unroll
    for (int o = 16; o > 0; o >>= 1)
        v += __shfl_down_sync(0xffffffffu, v, o);
    return v;
}

__global__ void __launch_bounds__(NTHREADS, 6) pmf_fused_kernel(
    const int*    __restrict__ user,
    const int*    __restrict__ item,
    const float*  __restrict__ ratings,
    const float4* __restrict__ ue,   // embedding row = 8 x float4 = one 128B line
    const float4* __restrict__ ve,
    float*        __restrict__ out)
{
    const int lane = threadIdx.x & 31;
    const int sub  = lane & 7;   // dim-chunk within 8-lane group
    const int grp  = lane >> 3;  // interaction-within-quad 0..3

    const bool b2 = (sub & 4) != 0;
    const bool b1 = (sub & 2) != 0;
    const bool b0 = (sub & 1) != 0;

    const int warp_id = (blockIdx.x * NTHREADS + threadIdx.x) >> 5;
    const int my_src  = (sub << 2) | grp;  // interaction this lane BCEs

    float bce = 0.0f, uu = 0.0f, vv = 0.0f;

    // software pipeline: preload chunk's indices one iteration ahead
    int c = warp_id;
    int   uidx = 0, iidx = 0;
    float rat  = 0.0f;
    if (c < NCHUNKS) {
        uidx = user[c * 32 + lane];
        iidx = item[c * 32 + lane];
        rat  = ratings[c * 32 + lane];
    }

    for (; c < NCHUNKS; ) {
        const int   cu = uidx;
        const int   ci = iidx;
        const float cr = rat;

        const int cn = c + NWARPS;
        if (cn < NCHUNKS) {
            uidx = user[cn * 32 + lane];
            iidx = item[cn * 32 + lane];
            rat  = ratings[cn * 32 + lane];
        }

        const float myr = __shfl_sync(0xffffffffu, cr, my_src);

        // 8 independent partial dots per lane -> loads batch freely (MLP up)
        float p[8];
        #pragma unroll
        for (int j = 0; j < 8; j++) {
            const int src = j * 4 + grp;
            const int ui = __shfl_sync(0xffffffffu, cu, src);
            const int ii = __shfl_sync(0xffffffffu, ci, src);

            // 8 lanes x float4 = 128B = one embedding row = one L2 line
            const float4 u = ue[ui * 8 + sub];
            const float4 v = ve[ii * 8 + sub];

            uu += u.x*u.x + u.y*u.y + u.z*u.z + u.w*u.w;
            vv += v.x*v.x + v.y*v.y + v.z*v.z + v.w*v.w;

            p[j] = u.x*v.x + u.y*v.y + u.z*v.z + u.w*v.w;
        }

        // Butterfly transpose-reduce: 7 shuffles total, one 3-level chain.
        // After level k, slot k holds partial sums for j = idx + (sub bits).
        float q[4];
        #pragma unroll
        for (int k = 0; k < 4; k++) {
            const float sent = b2 ? p[k] : p[k + 4];
            const float recv = __shfl_xor_sync(0xffffffffu, sent, 4);
            const float kept = b2 ? p[k + 4] : p[k];
            q[k] = kept + recv;
        }
        float r2[2];
        #pragma unroll
        for (int k = 0; k < 2; k++) {
            const float sent = b1 ? q[k] : q[k + 2];
            const float recv = __shfl_xor_sync(0xffffffffu, sent, 2);
            const float kept = b1 ? q[k + 2] : q[k];
            r2[k] = kept + recv;
        }
        {
            const float sent = b0 ? r2[0] : r2[1];
            const float recv = __shfl_xor_sync(0xffffffffu, sent, 1);
            const float kept = b0 ? r2[1] : r2[0];
            const float x = kept + recv;   // logit of interaction my_src

            // stable BCE: max(x,0) - x*r + log(1+exp(-|x|))
            bce += fmaxf(x, 0.0f) - x * myr + __logf(1.0f + __expf(-fabsf(x)));
        }

        c = cn;
    }

    // ---- block reduction (double) ----
    __shared__ double s_b[8], s_u[8], s_v[8];
    __shared__ bool   s_last;
    const int wib = threadIdx.x >> 5;

    double db = warp_reduce_d((double)bce);
    double du = warp_reduce_d((double)uu);
    double dv = warp_reduce_d((double)vv);
    if (lane == 0) { s_b[wib] = db; s_u[wib] = du; s_v[wib] = dv; }
    __syncthreads();

    if (threadIdx.x == 0) {
        double bsum = 0.0, usum = 0.0, vsum = 0.0;
        #pragma unroll
        for (int i = 0; i < NTHREADS / 32; i++) { bsum += s_b[i]; usum += s_u[i]; vsum += s_v[i]; }
        g_part[blockIdx.x][0] = bsum;
        g_part[blockIdx.x][1] = usum;
        g_part[blockIdx.x][2] = vsum;
        __threadfence();
        unsigned int t = atomicAdd(&g_ticket, 1u);
        bool last = (t == NBLOCKS - 1);
        if (last) g_ticket = 0;
        s_last = last;
    }
    __syncthreads();

    if (s_last) {
        __threadfence();
        double b = 0.0, u = 0.0, v = 0.0;
        for (int i = threadIdx.x; i < NBLOCKS; i += NTHREADS) {
            b += g_part[i][0];
            u += g_part[i][1];
            v += g_part[i][2];
        }
        b = warp_reduce_d(b);
        u = warp_reduce_d(u);
        v = warp_reduce_d(v);
        if (lane == 0) { s_b[wib] = b; s_u[wib] = u; s_v[wib] = v; }
        __syncthreads();
        if (threadIdx.x == 0) {
            double fb = 0.0, fu = 0.0, fv = 0.0;
            #pragma unroll
            for (int i = 0; i < NTHREADS / 32; i++) { fb += s_b[i]; fu += s_u[i]; fv += s_v[i]; }
            out[0] = (float)(fb + LAM * sqrt(fu) + LAM * sqrt(fv));
        }
    }
}

extern "C" void kernel_launch(void* const* d_in, const int* in_sizes, int n_in,
                              void* d_out, int out_size) {
    const int*    user = (const int*)d_in[0];
    const int*    item = (const int*)d_in[1];
    const float*  rat  = (const float*)d_in[2];
    const float4* ue   = (const float4*)d_in[3];
    const float4* ve   = (const float4*)d_in[4];
    float* out = (float*)d_out;

    pmf_fused_kernel<<<NBLOCKS, NTHREADS>>>(user, item, rat, ue, ve, out);
}

// round 6
// speedup vs baseline: 1.1671x; 1.1671x over previous
#include <cuda_runtime.h>
#include <math.h>

#define BATCH     2000000
#define LAM       0.1
#define NBLOCKS   1184      // 148 SMs * 8
#define NTHREADS  256
#define NWARPS    ((NBLOCKS * NTHREADS) >> 5)
#define NCHUNKS   (BATCH / 32)

__device__ double g_part[NBLOCKS][3];
__device__ unsigned int g_ticket;   // zero-init; last block resets -> graph-replay safe

__device__ __forceinline__ double warp_reduce_d(double v) {
    #pragma unroll
    for (int o = 16; o > 0; o >>= 1)
        v += __shfl_down_sync(0xffffffffu, v, o);
    return v;
}

__global__ void __launch_bounds__(NTHREADS, 8) pmf_fused_kernel(
    const int*    __restrict__ user,
    const int*    __restrict__ item,
    const float*  __restrict__ ratings,
    const float4* __restrict__ ue,   // embedding row = 8 x float4 = one 128B line
    const float4* __restrict__ ve,
    float*        __restrict__ out)
{
    const int lane = threadIdx.x & 31;
    const int sub  = lane & 7;   // dim-chunk within 8-lane group; also "my" j
    const int grp  = lane >> 3;  // interaction-within-quad 0..3

    const int warp_id = (blockIdx.x * NTHREADS + threadIdx.x) >> 5;
    const int my_src  = (sub << 2) | grp;  // interaction this lane BCEs (lane bijection)

    float bce = 0.0f, uu = 0.0f, vv = 0.0f;

    // software pipeline: preload chunk's indices one iteration ahead.
    // my_src is a permutation of 0..31 -> ratings load stays fully coalesced,
    // and each lane directly owns the rating it needs (no shuffle).
    int c = warp_id;
    int   uidx = 0, iidx = 0;
    float rat  = 0.0f;
    if (c < NCHUNKS) {
        uidx = __ldcs(user    + c * 32 + lane);
        iidx = __ldcs(item    + c * 32 + lane);
        rat  = __ldcs(ratings + c * 32 + my_src);
    }

    for (; c < NCHUNKS; ) {
        const int   cu  = uidx;
        const int   ci  = iidx;
        const float myr = rat;

        const int cn = c + NWARPS;
        if (cn < NCHUNKS) {
            uidx = __ldcs(user    + cn * 32 + lane);
            iidx = __ldcs(item    + cn * 32 + lane);
            rat  = __ldcs(ratings + cn * 32 + my_src);
        }

        float mylogit = 0.0f;

        #pragma unroll
        for (int j = 0; j < 8; j++) {
            const int src = j * 4 + grp;
            const int ui = __shfl_sync(0xffffffffu, cu, src);
            const int ii = __shfl_sync(0xffffffffu, ci, src);

            // 8 lanes x float4 = 128B = one embedding row = one L2 line
            const float4 u = ue[ui * 8 + sub];
            const float4 v = ve[ii * 8 + sub];

            uu += u.x*u.x + u.y*u.y + u.z*u.z + u.w*u.w;
            vv += v.x*v.x + v.y*v.y + v.z*v.z + v.w*v.w;

            float p = u.x*v.x + u.y*v.y + u.z*v.z + u.w*v.w;
            p += __shfl_xor_sync(0xffffffffu, p, 4);
            p += __shfl_xor_sync(0xffffffffu, p, 2);
            p += __shfl_xor_sync(0xffffffffu, p, 1);

            if (sub == j) mylogit = p;   // bijective lane<->interaction keep
        }

        // one BCE per lane per chunk, all lanes active:
        // max(x,0) - x*r + log(1 + exp(-|x|))
        const float x = mylogit;
        bce += fmaxf(x, 0.0f) - x * myr + __logf(1.0f + __expf(-fabsf(x)));

        c = cn;
    }

    // ---- block reduction (double) ----
    __shared__ double s_b[8], s_u[8], s_v[8];
    __shared__ bool   s_last;
    const int wib = threadIdx.x >> 5;

    double db = warp_reduce_d((double)bce);
    double du = warp_reduce_d((double)uu);
    double dv = warp_reduce_d((double)vv);
    if (lane == 0) { s_b[wib] = db; s_u[wib] = du; s_v[wib] = dv; }
    __syncthreads();

    if (threadIdx.x == 0) {
        double bsum = 0.0, usum = 0.0, vsum = 0.0;
        #pragma unroll
        for (int i = 0; i < NTHREADS / 32; i++) { bsum += s_b[i]; usum += s_u[i]; vsum += s_v[i]; }
        g_part[blockIdx.x][0] = bsum;
        g_part[blockIdx.x][1] = usum;
        g_part[blockIdx.x][2] = vsum;
        __threadfence();
        unsigned int t = atomicAdd(&g_ticket, 1u);
        bool last = (t == NBLOCKS - 1);
        if (last) g_ticket = 0;
        s_last = last;
    }
    __syncthreads();

    if (s_last) {
        __threadfence();
        double b = 0.0, u = 0.0, v = 0.0;
        for (int i = threadIdx.x; i < NBLOCKS; i += NTHREADS) {
            b += g_part[i][0];
            u += g_part[i][1];
            v += g_part[i][2];
        }
        b = warp_reduce_d(b);
        u = warp_reduce_d(u);
        v = warp_reduce_d(v);
        if (lane == 0) { s_b[wib] = b; s_u[wib] = u; s_v[wib] = v; }
        __syncthreads();
        if (threadIdx.x == 0) {
            double fb = 0.0, fu = 0.0, fv = 0.0;
            #pragma unroll
            for (int i = 0; i < NTHREADS / 32; i++) { fb += s_b[i]; fu += s_u[i]; fv += s_v[i]; }
            out[0] = (float)(fb + LAM * sqrt(fu) + LAM * sqrt(fv));
        }
    }
}

extern "C" void kernel_launch(void* const* d_in, const int* in_sizes, int n_in,
                              void* d_out, int out_size) {
    const int*    user = (const int*)d_in[0];
    const int*    item = (const int*)d_in[1];
    const float*  rat  = (const float*)d_in[2];
    const float4* ue   = (const float4*)d_in[3];
    const float4* ve   = (const float4*)d_in[4];
    float* out = (float*)d_out;

    pmf_fused_kernel<<<NBLOCKS, NTHREADS>>>(user, item, rat, ue, ve, out);
}